// round 4
// baseline (speedup 1.0000x reference)
#include <cuda_runtime.h>

// x: (16, 2, 1024, 1024) fp32, 20 diffusion steps, depthwise 5-point stencil,
// reflect padding. Temporal blocking: K=5 fused steps per pass, 4 passes.
// Round 4: float2 per thread + 512-thread blocks -> ~60 regs/thread ->
// 2 blocks/SM = 32 warps/SM (vs 16), doubling latency-hiding capacity.
#define HH 1024
#define WW 1024
#define NPLANES 32
#define PLANE_ELEMS (HH * WW)
#define K 5            // fused timesteps per kernel pass
#define RB 128         // output rows per block
#define NT 512         // threads per block (float2 each -> 1024 cols)
#define NW (NT / 32)   // 16 warps

// 128 MB ping-pong scratch (device global — allocation-free).
__device__ float g_scratch[NPLANES * PLANE_ELEMS];

__device__ __forceinline__ int reflect_row(int i) {
    i = (i < 0) ? -i : i;
    return (i >= HH) ? (2 * HH - 2 - i) : i;
}

__global__ __launch_bounds__(NT, 2)
void fused_stencil(const float* __restrict__ src,
                   float* __restrict__ dst,
                   const float* __restrict__ wgt)
{
    // Per-warp edge exchange (lane0 .x / lane31 .y), double-buffered per row.
    __shared__ float eX[2][K][NW];
    __shared__ float eW[2][K][NW];

    const int band = blockIdx.x;
    const int img  = blockIdx.y;
    const int t    = threadIdx.x;     // column group: cols 2t, 2t+1
    const int lane = t & 31;
    const int warp = t >> 5;

    const float* wp = wgt + (img & 1) * 9;   // OIHW (2,1,3,3), depthwise
    const float wu = wp[1];
    const float wl = wp[3];
    const float wc = wp[4];
    const float wr = wp[5];
    const float wd = wp[7];

    const float* sp = src + (size_t)img * PLANE_ELEMS;
    float*       dp = dst + (size_t)img * PLANE_ELEMS;

    const int r0 = band * RB;

    // Rolling window per stage s: a[s] = u_s[row-2], b[s] = u_s[row-1]
    float2 a[K], b[K];
#pragma unroll
    for (int s = 0; s < K; ++s) {
        a[s] = make_float2(0.f, 0.f);
        b[s] = make_float2(0.f, 0.f);
    }

    // Zero edge buffers so iteration 0 reads match b == 0.
    if (t < 2 * K * NW) {
        ((float*)eX)[t] = 0.f;
        ((float*)eW)[t] = 0.f;
    }
    __syncthreads();

    const int niter = RB + 2 * K;   // 138

    // Prefetch pipeline, depth 2.
    float2 p0 = ((const float2*)(sp + (size_t)reflect_row(r0 - K)     * WW))[t];
    float2 p1 = ((const float2*)(sp + (size_t)reflect_row(r0 - K + 1) * WW))[t];

#pragma unroll 2
    for (int m = 0; m < niter; ++m) {
        const int i = r0 - K + m;   // input row index for stage 0

        float2 cur[K + 1];
        cur[0] = p0;
        p0 = p1;
        if (m + 2 < niter) {
            p1 = ((const float2*)(sp + (size_t)reflect_row(i + 2) * WW))[t];
        }

        const int rd = m & 1;       // edge buffer written at end of iter m-1

#pragma unroll
        for (int s = 1; s <= K; ++s) {
            const float2 bb = b[s - 1];   // u_{s-1}[j]   (center)
            const float2 aa = a[s - 1];   // u_{s-1}[j-1] (up)
            const float2 dd = cur[s - 1]; // u_{s-1}[j+1] (down)

            float lv = __shfl_up_sync(0xffffffffu, bb.y, 1);
            float rv = __shfl_down_sync(0xffffffffu, bb.x, 1);
            if (lane == 0)  lv = (t == 0)      ? bb.y : eW[rd][s - 1][warp - 1];
            if (lane == 31) rv = (t == NT - 1) ? bb.x : eX[rd][s - 1][warp + 1];

            float2 o;
            o.x = fmaf(wu, aa.x, fmaf(wd, dd.x, fmaf(wl, lv,   fmaf(wr, bb.y, wc * bb.x))));
            o.y = fmaf(wu, aa.y, fmaf(wd, dd.y, fmaf(wl, bb.x, fmaf(wr, rv,   wc * bb.y))));
            cur[s] = o;
        }

        // Final-stage row j = i - K is a band row exactly when m >= 2K.
        if (m >= 2 * K) {
            ((float2*)(dp + (size_t)(i - K) * WW))[t] = cur[K];
        }

        // Shift windows; publish edges for next iteration (other parity).
#pragma unroll
        for (int s = 0; s < K; ++s) {
            a[s] = b[s];
            b[s] = cur[s];
        }
        const int wrb = (m + 1) & 1;
        if (lane == 0) {
#pragma unroll
            for (int s = 0; s < K; ++s) eX[wrb][s][warp] = b[s].x;
        }
        if (lane == 31) {
#pragma unroll
            for (int s = 0; s < K; ++s) eW[wrb][s][warp] = b[s].y;
        }
        __syncthreads();
    }
}

extern "C" void kernel_launch(void* const* d_in, const int* in_sizes, int n_in,
                              void* d_out, int out_size)
{
    const float* x   = (const float*)d_in[0];
    const float* wgt = (const float*)d_in[1];
    float* out = (float*)d_out;

    float* scratch = nullptr;
    cudaGetSymbolAddress((void**)&scratch, g_scratch);

    dim3 grid(HH / RB, NPLANES);   // 8 bands x 32 planes = 256 blocks
    dim3 block(NT);                // 512 threads (float2 each)

    // 4 passes of 5 fused steps: x -> scratch -> out -> scratch -> out
    fused_stencil<<<grid, block>>>(x,       scratch, wgt);
    fused_stencil<<<grid, block>>>(scratch, out,     wgt);
    fused_stencil<<<grid, block>>>(out,     scratch, wgt);
    fused_stencil<<<grid, block>>>(scratch, out,     wgt);
}

// round 5
// speedup vs baseline: 1.1645x; 1.1645x over previous
#include <cuda_runtime.h>

// x: (16, 2, 1024, 1024) fp32, 20 diffusion steps, depthwise 5-point stencil,
// reflect padding. Temporal blocking: K=5 fused steps/pass, 4 passes.
// Round 5: R3 float4 structure + packed fma.rn.f32x2 (FFMA2) — halves
// fma-pipe instruction count per stencil stage.
#define HH 1024
#define WW 1024
#define NPLANES 32
#define PLANE_ELEMS (HH * WW)
#define K 5
#define RB 128

__device__ float g_scratch[NPLANES * PLANE_ELEMS];

typedef unsigned long long ull;

__device__ __forceinline__ float2 f2fma(float2 a, float2 b, float2 c) {
    ull ua = *reinterpret_cast<ull*>(&a);
    ull ub = *reinterpret_cast<ull*>(&b);
    ull uc = *reinterpret_cast<ull*>(&c);
    ull ud;
    asm("fma.rn.f32x2 %0, %1, %2, %3;" : "=l"(ud) : "l"(ua), "l"(ub), "l"(uc));
    return *reinterpret_cast<float2*>(&ud);
}

__device__ __forceinline__ float2 f2mul(float2 a, float2 b) {
    ull ua = *reinterpret_cast<ull*>(&a);
    ull ub = *reinterpret_cast<ull*>(&b);
    ull ud;
    asm("mul.rn.f32x2 %0, %1, %2;" : "=l"(ud) : "l"(ua), "l"(ub));
    return *reinterpret_cast<float2*>(&ud);
}

__device__ __forceinline__ int reflect_row(int i) {
    i = (i < 0) ? -i : i;
    return (i >= HH) ? (2 * HH - 2 - i) : i;
}

__global__ __launch_bounds__(256, 2)
void fused_stencil(const float* __restrict__ src,
                   float* __restrict__ dst,
                   const float* __restrict__ wgt)
{
    // Per-warp edge exchange (lane0 col0 / lane31 col3), double-buffered per row.
    __shared__ float eX[2][K][8];
    __shared__ float eW[2][K][8];

    const int band = blockIdx.x;
    const int img  = blockIdx.y;
    const int t    = threadIdx.x;     // column group: cols 4t..4t+3
    const int lane = t & 31;
    const int warp = t >> 5;

    const float* wp = wgt + (img & 1) * 9;   // OIHW (2,1,3,3), depthwise
    const float2 wuu = make_float2(wp[1], wp[1]);
    const float2 wll = make_float2(wp[3], wp[3]);
    const float2 wcc = make_float2(wp[4], wp[4]);
    const float2 wrr = make_float2(wp[5], wp[5]);
    const float2 wdd = make_float2(wp[7], wp[7]);

    const float* sp = src + (size_t)img * PLANE_ELEMS;
    float*       dp = dst + (size_t)img * PLANE_ELEMS;

    const int r0 = band * RB;

    // Rolling window per stage s: a = u_s[row-2], b = u_s[row-1]; each row
    // split into two packed float2 halves (cols 0-1 and 2-3 of the group).
    float2 a01[K], a23[K], b01[K], b23[K];
#pragma unroll
    for (int s = 0; s < K; ++s) {
        a01[s] = make_float2(0.f, 0.f); a23[s] = make_float2(0.f, 0.f);
        b01[s] = make_float2(0.f, 0.f); b23[s] = make_float2(0.f, 0.f);
    }

    if (t < 2 * K * 8) {
        ((float*)eX)[t] = 0.f;
        ((float*)eW)[t] = 0.f;
    }
    __syncthreads();

    const int niter = RB + 2 * K;   // 138

    float4 p0 = ((const float4*)(sp + (size_t)reflect_row(r0 - K)     * WW))[t];
    float4 p1 = ((const float4*)(sp + (size_t)reflect_row(r0 - K + 1) * WW))[t];

#pragma unroll 2
    for (int m = 0; m < niter; ++m) {
        const int i = r0 - K + m;   // input row index for stage 0

        float2 c01[K + 1], c23[K + 1];
        c01[0] = make_float2(p0.x, p0.y);
        c23[0] = make_float2(p0.z, p0.w);
        p0 = p1;
        if (m + 2 < niter) {
            p1 = ((const float4*)(sp + (size_t)reflect_row(i + 2) * WW))[t];
        }

        const int rd = m & 1;

#pragma unroll
        for (int s = 1; s <= K; ++s) {
            const float2 B01 = b01[s - 1], B23 = b23[s - 1];   // center row
            const float2 A01 = a01[s - 1], A23 = a23[s - 1];   // up row
            const float2 D01 = c01[s - 1], D23 = c23[s - 1];   // down row

            float lv = __shfl_up_sync(0xffffffffu, B23.y, 1);
            float rv = __shfl_down_sync(0xffffffffu, B01.x, 1);
            if (lane == 0)  lv = (t == 0)   ? B01.y : eW[rd][s - 1][warp - 1];
            if (lane == 31) rv = (t == 255) ? B23.x : eX[rd][s - 1][warp + 1];

            // Shifted packed pairs: left of (x,y) / mid shared / right of (z,w)
            const float2 Lxy = make_float2(lv,    B01.x);
            const float2 mid = make_float2(B01.y, B23.x);
            const float2 Rzw = make_float2(B23.y, rv);

            float2 o01 = f2mul(wcc, B01);
            o01 = f2fma(wuu, A01, o01);
            o01 = f2fma(wdd, D01, o01);
            o01 = f2fma(wll, Lxy, o01);
            o01 = f2fma(wrr, mid, o01);

            float2 o23 = f2mul(wcc, B23);
            o23 = f2fma(wuu, A23, o23);
            o23 = f2fma(wdd, D23, o23);
            o23 = f2fma(wll, mid, o23);
            o23 = f2fma(wrr, Rzw, o23);

            c01[s] = o01;
            c23[s] = o23;
        }

        if (m >= 2 * K) {
            ((float4*)(dp + (size_t)(i - K) * WW))[t] =
                make_float4(c01[K].x, c01[K].y, c23[K].x, c23[K].y);
        }

#pragma unroll
        for (int s = 0; s < K; ++s) {
            a01[s] = b01[s]; a23[s] = b23[s];
            b01[s] = c01[s]; b23[s] = c23[s];
        }
        const int wrb = (m + 1) & 1;
        if (lane == 0) {
#pragma unroll
            for (int s = 0; s < K; ++s) eX[wrb][s][warp] = b01[s].x;
        }
        if (lane == 31) {
#pragma unroll
            for (int s = 0; s < K; ++s) eW[wrb][s][warp] = b23[s].y;
        }
        __syncthreads();
    }
}

extern "C" void kernel_launch(void* const* d_in, const int* in_sizes, int n_in,
                              void* d_out, int out_size)
{
    const float* x   = (const float*)d_in[0];
    const float* wgt = (const float*)d_in[1];
    float* out = (float*)d_out;

    float* scratch = nullptr;
    cudaGetSymbolAddress((void**)&scratch, g_scratch);

    dim3 grid(HH / RB, NPLANES);   // 8 bands x 32 planes = 256 blocks
    dim3 block(WW / 4);            // 256 threads

    fused_stencil<<<grid, block>>>(x,       scratch, wgt);
    fused_stencil<<<grid, block>>>(scratch, out,     wgt);
    fused_stencil<<<grid, block>>>(out,     scratch, wgt);
    fused_stencil<<<grid, block>>>(scratch, out,     wgt);
}

// round 6
// speedup vs baseline: 1.5935x; 1.3684x over previous
#include <cuda_runtime.h>

// x: (16, 2, 1024, 1024) fp32, 20 diffusion steps, depthwise 5-point stencil,
// reflect padding. Temporal blocking: K=5 fused steps/pass, 4 passes.
// Round 6: fully warp-independent column strips with redundant halo compute.
// No __syncthreads, no smem — horizontal neighbors via shuffles only; strips
// overlap so edge-garbage (1 col/side/stage) never reaches stored columns.
#define HH 1024
#define WW 1024
#define NPLANES 32
#define PLANE_ELEMS (HH * WW)
#define K 5            // fused timesteps per pass
#define RB 128         // output rows per warp
#define NSTRIP 9       // strip j input base = 112*j, window 128 cols

__device__ float g_scratch[NPLANES * PLANE_ELEMS];

__device__ __forceinline__ int reflect_row(int i) {
    i = (i < 0) ? -i : i;
    return (i >= HH) ? (2 * HH - 2 - i) : i;
}

__global__ __launch_bounds__(256, 2)
void fused_stencil(const float* __restrict__ src,
                   float* __restrict__ dst,
                   const float* __restrict__ wgt)
{
    const int strip = blockIdx.x;          // 0..8
    const int img   = blockIdx.y;          // 0..31
    const int warp  = threadIdx.x >> 5;    // band index 0..7
    const int lane  = threadIdx.x & 31;

    const bool ledge = (strip == 0);
    const bool redge = (strip == NSTRIP - 1);

    const float* wp = wgt + (img & 1) * 9;   // OIHW (2,1,3,3), depthwise
    const float wu = wp[1];
    const float wl = wp[3];
    const float wc = wp[4];
    const float wr = wp[5];
    const float wd = wp[7];

    const float* sp = src + (size_t)img * PLANE_ELEMS;
    float*       dp = dst + (size_t)img * PLANE_ELEMS;

    const int base = strip * 112;          // strip input col base (4-aligned)
    const int g    = (base >> 2) + lane;   // float4 index of this lane's cols
    const int r0   = warp * RB;

    // Store predicate: interior strips keep lanes 2..29; edge strips extend
    // to the domain boundary (mirror trick makes those cols valid).
    const int lo = ledge ? 0 : 2;
    const int hi = redge ? 31 : 29;
    const bool do_store = (lane >= lo && lane <= hi);

    // Rolling window per stage s: a[s] = u_s[row-2], b[s] = u_s[row-1]
    float4 a[K], b[K];
#pragma unroll
    for (int s = 0; s < K; ++s) {
        a[s] = make_float4(0.f, 0.f, 0.f, 0.f);
        b[s] = make_float4(0.f, 0.f, 0.f, 0.f);
    }

    const int niter = RB + 2 * K;   // 138

    // Prefetch pipeline, depth 2.
    float4 p0 = ((const float4*)(sp + (size_t)reflect_row(r0 - K)     * WW))[g];
    float4 p1 = ((const float4*)(sp + (size_t)reflect_row(r0 - K + 1) * WW))[g];

#pragma unroll 2
    for (int m = 0; m < niter; ++m) {
        const int i = r0 - K + m;   // input row index for stage 0

        float4 cur[K + 1];
        cur[0] = p0;
        p0 = p1;
        if (m + 2 < niter) {
            p1 = ((const float4*)(sp + (size_t)reflect_row(i + 2) * WW))[g];
        }

#pragma unroll
        for (int s = 1; s <= K; ++s) {
            const float4 bb = b[s - 1];   // u_{s-1}[j]   (center)
            const float4 aa = a[s - 1];   // u_{s-1}[j-1] (up)
            const float4 dd = cur[s - 1]; // u_{s-1}[j+1] (down)

            // Horizontal neighbors: shuffles only. Lane-0/31 receive their own
            // value (garbage) on interior strips — those columns are in the
            // redundant halo and never stored. At true domain edges apply the
            // mirror: col -1 -> col 1, col 1023+1 -> col 1022.
            float lv = __shfl_up_sync(0xffffffffu, bb.w, 1);
            float rv = __shfl_down_sync(0xffffffffu, bb.x, 1);
            if (ledge && lane == 0)  lv = bb.y;
            if (redge && lane == 31) rv = bb.z;

            float4 o;
            o.x = fmaf(wu, aa.x, fmaf(wd, dd.x, fmaf(wl, lv,   fmaf(wr, bb.y, wc * bb.x))));
            o.y = fmaf(wu, aa.y, fmaf(wd, dd.y, fmaf(wl, bb.x, fmaf(wr, bb.z, wc * bb.y))));
            o.z = fmaf(wu, aa.z, fmaf(wd, dd.z, fmaf(wl, bb.y, fmaf(wr, bb.w, wc * bb.z))));
            o.w = fmaf(wu, aa.w, fmaf(wd, dd.w, fmaf(wl, bb.z, fmaf(wr, rv,   wc * bb.w))));
            cur[s] = o;
        }

        // Final-stage row j = i - K is a band row exactly when m >= 2K.
        if (m >= 2 * K && do_store) {
            ((float4*)(dp + (size_t)(i - K) * WW))[g] = cur[K];
        }

#pragma unroll
        for (int s = 0; s < K; ++s) {
            a[s] = b[s];
            b[s] = cur[s];
        }
    }
}

extern "C" void kernel_launch(void* const* d_in, const int* in_sizes, int n_in,
                              void* d_out, int out_size)
{
    const float* x   = (const float*)d_in[0];
    const float* wgt = (const float*)d_in[1];
    float* out = (float*)d_out;

    float* scratch = nullptr;
    cudaGetSymbolAddress((void**)&scratch, g_scratch);

    dim3 grid(NSTRIP, NPLANES);   // 9 strips x 32 planes = 288 blocks
    dim3 block(256);              // 8 warps = 8 row bands

    // 4 passes of 5 fused steps: x -> scratch -> out -> scratch -> out
    fused_stencil<<<grid, block>>>(x,       scratch, wgt);
    fused_stencil<<<grid, block>>>(scratch, out,     wgt);
    fused_stencil<<<grid, block>>>(out,     scratch, wgt);
    fused_stencil<<<grid, block>>>(scratch, out,     wgt);
}

// round 7
// speedup vs baseline: 2.3028x; 1.4451x over previous
#include <cuda_runtime.h>

// x: (16, 2, 1024, 1024) fp32, 20 diffusion steps, depthwise 5-point stencil,
// reflect padding. Temporal blocking: K=5 fused steps/pass, 4 passes.
// Round 7: R6 strips + (a) all shuffles hoisted to iteration top (operands are
// iteration-start state), (b) branch-free SEL edge fixups, (c) dd-last FMA
// trees (1-FMA inter-stage chain), (d) unconditional branch-free prefetch.
#define HH 1024
#define WW 1024
#define NPLANES 32
#define PLANE_ELEMS (HH * WW)
#define K 5            // fused timesteps per pass
#define RB 128         // output rows per warp
#define NSTRIP 9       // strip j input base = 112*j, window 128 cols

__device__ float g_scratch[NPLANES * PLANE_ELEMS];

__device__ __forceinline__ int reflect_row(int i) {
    i = (i < 0) ? -i : i;
    return (i >= HH) ? (2 * HH - 2 - i) : i;
}

__global__ __launch_bounds__(256, 2)
void fused_stencil(const float* __restrict__ src,
                   float* __restrict__ dst,
                   const float* __restrict__ wgt)
{
    const int strip = blockIdx.x;          // 0..8
    const int img   = blockIdx.y;          // 0..31
    const int warp  = threadIdx.x >> 5;    // band index 0..7
    const int lane  = threadIdx.x & 31;

    const bool ledge = (strip == 0);
    const bool redge = (strip == NSTRIP - 1);

    const float* wp = wgt + (img & 1) * 9;   // OIHW (2,1,3,3), depthwise
    const float wu = wp[1];
    const float wl = wp[3];
    const float wc = wp[4];
    const float wr = wp[5];
    const float wd = wp[7];

    const float* sp = src + (size_t)img * PLANE_ELEMS;
    float*       dp = dst + (size_t)img * PLANE_ELEMS;

    const int base = strip * 112;          // strip input col base (4-aligned)
    const int g    = (base >> 2) + lane;   // float4 index of this lane's cols
    const int r0   = warp * RB;

    // Interior strips keep lanes 2..29; edge strips extend to the boundary.
    const int lo = ledge ? 0 : 2;
    const int hi = redge ? 31 : 29;
    const bool do_store = (lane >= lo && lane <= hi);

    // Per-lane edge-fix predicates (uniform-strip && lane test), branch-free.
    const bool fixL = ledge && (lane == 0);
    const bool fixR = redge && (lane == 31);

    // Rolling window per stage s: a[s] = u_s[row-2], b[s] = u_s[row-1]
    float4 a[K], b[K];
#pragma unroll
    for (int s = 0; s < K; ++s) {
        a[s] = make_float4(0.f, 0.f, 0.f, 0.f);
        b[s] = make_float4(0.f, 0.f, 0.f, 0.f);
    }

    const int niter = RB + 2 * K;   // 138

    // Prefetch pipeline, depth 2 (always-on; reflect keeps rows in-bounds).
    float4 p0 = ((const float4*)(sp + (size_t)reflect_row(r0 - K)     * WW))[g];
    float4 p1 = ((const float4*)(sp + (size_t)reflect_row(r0 - K + 1) * WW))[g];

#pragma unroll 2
    for (int m = 0; m < niter; ++m) {
        const int i = r0 - K + m;   // input row index for stage 0

        // Shuffle batch: all horizontal neighbors depend ONLY on the b[] state
        // at iteration start — issue them together so latency pipelines.
        float lv[K], rv[K];
#pragma unroll
        for (int s = 0; s < K; ++s) {
            const float lu = __shfl_up_sync(0xffffffffu, b[s].w, 1);
            const float rd = __shfl_down_sync(0xffffffffu, b[s].x, 1);
            lv[s] = fixL ? b[s].y : lu;   // mirror col -1 -> col 1
            rv[s] = fixR ? b[s].z : rd;   // mirror col 1024 -> col 1022
        }

        float4 cur[K + 1];
        cur[0] = p0;
        p0 = p1;
        p1 = ((const float4*)(sp + (size_t)reflect_row(i + 2) * WW))[g];

#pragma unroll
        for (int s = 1; s <= K; ++s) {
            const float4 B = b[s - 1];    // center row (iter-start state)
            const float4 A = a[s - 1];    // up row     (iter-start state)
            const float4 D = cur[s - 1];  // down row   (fresh — keep last)

            // base = wc*B + wl*left + wr*right + wu*A  (no fresh deps)
            float4 bs;
            bs.x = fmaf(wu, A.x, fmaf(wl, lv[s - 1], fmaf(wr, B.y, wc * B.x)));
            bs.y = fmaf(wu, A.y, fmaf(wl, B.x,       fmaf(wr, B.z, wc * B.y)));
            bs.z = fmaf(wu, A.z, fmaf(wl, B.y,       fmaf(wr, B.w, wc * B.z)));
            bs.w = fmaf(wu, A.w, fmaf(wl, B.z,       fmaf(wr, rv[s - 1], wc * B.w)));

            float4 o;
            o.x = fmaf(wd, D.x, bs.x);
            o.y = fmaf(wd, D.y, bs.y);
            o.z = fmaf(wd, D.z, bs.z);
            o.w = fmaf(wd, D.w, bs.w);
            cur[s] = o;
        }

        // Final-stage row j = i - K is a band row exactly when m >= 2K.
        if (m >= 2 * K && do_store) {
            ((float4*)(dp + (size_t)(i - K) * WW))[g] = cur[K];
        }

#pragma unroll
        for (int s = 0; s < K; ++s) {
            a[s] = b[s];
            b[s] = cur[s];
        }
    }
}

extern "C" void kernel_launch(void* const* d_in, const int* in_sizes, int n_in,
                              void* d_out, int out_size)
{
    const float* x   = (const float*)d_in[0];
    const float* wgt = (const float*)d_in[1];
    float* out = (float*)d_out;

    float* scratch = nullptr;
    cudaGetSymbolAddress((void**)&scratch, g_scratch);

    dim3 grid(NSTRIP, NPLANES);   // 9 strips x 32 planes = 288 blocks
    dim3 block(256);              // 8 warps = 8 row bands

    // 4 passes of 5 fused steps: x -> scratch -> out -> scratch -> out
    fused_stencil<<<grid, block>>>(x,       scratch, wgt);
    fused_stencil<<<grid, block>>>(scratch, out,     wgt);
    fused_stencil<<<grid, block>>>(out,     scratch, wgt);
    fused_stencil<<<grid, block>>>(scratch, out,     wgt);
}